// round 12
// baseline (speedup 1.0000x reference)
#include <cuda_runtime.h>
#include <cuda_fp16.h>
#include <math.h>
#include <cstdint>

#define S_  2048
#define B_  8
#define E_  1024
#define SB_ (S_*B_)
#define G4_ (4*E_)

/* ---------------- static device scratch (no runtime allocation) ---------------- */
__device__ float g_xln  [SB_*E_];
__device__ float g_gx   [(size_t)SB_*G4_];
__device__ float g_rnn  [SB_*E_];
__device__ float g_mh   [SB_*E_];
__device__ float g_hmid [SB_*E_];
__device__ float g_qpre [SB_*E_];
__device__ float g_query[SB_*E_];
__device__ float g_scores[(size_t)B_*S_*S_];
__device__ float g_h2   [SB_*E_];
__device__ float g_xff  [SB_*E_];
__device__ float g_lnffo[SB_*E_];
__device__ float g_tbuf [2*E_];
__device__ float g_vsgv [E_];
__device__ float g_hbuf [2][B_*E_];
__device__ unsigned g_bar_cnt;
__device__ unsigned g_bar_gen;

/* fp16 mirrors for tensor-core GEMM inputs */
__device__ __half gh_xln [SB_*E_];
__device__ __half gh_Wih [(size_t)G4_*E_];
__device__ __half gh_hmid[SB_*E_];
__device__ __half gh_qlW [(size_t)E_*E_];
__device__ __half gh_qsc [SB_*E_];
__device__ __half gh_ksc [SB_*E_];
__device__ __half gh_vT  [(size_t)B_*E_*S_];
__device__ __half gh_sc  [(size_t)B_*S_*S_];
__device__ __half gh_xff [SB_*E_];
__device__ __half gh_bmW [(size_t)E_*E_];

__device__ __forceinline__ float fsigm(float x){ return 1.0f/(1.0f+__expf(-x)); }
__device__ __forceinline__ float psigm(float x){ return 1.0f/(1.0f+expf(-x)); }
__device__ __forceinline__ uint32_t s2u(const void* p){
    return (uint32_t)__cvta_generic_to_shared(p);
}
#define CP_A16(dst, src) \
    asm volatile("cp.async.cg.shared.global [%0], [%1], 16;" :: "r"(dst), "l"(src))
#define CP_COMMIT() asm volatile("cp.async.commit_group;" ::: "memory")
#define CP_WAIT1()  asm volatile("cp.async.wait_group 1;" ::: "memory")
#define CP_WAIT0()  asm volatile("cp.async.wait_group 0;" ::: "memory")
#define LDSM_X4(r0,r1,r2,r3,addr) \
    asm volatile("ldmatrix.sync.aligned.m8n8.x4.shared.b16 {%0,%1,%2,%3}, [%4];" \
        : "=r"(r0), "=r"(r1), "=r"(r2), "=r"(r3) : "r"(addr))
#define MMA_F16(c, a, b0, b1) \
    asm volatile("mma.sync.aligned.m16n8k16.row.col.f32.f16.f16.f32 " \
        "{%0,%1,%2,%3}, {%4,%5,%6,%7}, {%8,%9}, {%0,%1,%2,%3};" \
        : "+f"((c)[0]), "+f"((c)[1]), "+f"((c)[2]), "+f"((c)[3]) \
        : "r"((a)[0]), "r"((a)[1]), "r"((a)[2]), "r"((a)[3]), "r"(b0), "r"(b1))

/* ---------------- fp16 tensor-core GEMM 128x128, K-tile 32, cp.async x2 --------
   NT: A[M,K] lda, B[N,K] ldb, half inputs, fp32 out.  Batched via blockIdx.z.
   mode 0: acc + bias[n] (+ bias2[n])
   mode 1: acc*alpha + extra[m,n]; causal: tile n0>m0 -> copy extra (mask)
   mode 2: acc + extra[m,n];       causal: K limited to m0+128
   mode 3: gelu(acc+bias[n]) + extra[m,n]                                        */
#define LDH 40
__global__ void __launch_bounds__(256) gemm_h(
    const __half* __restrict__ A, const __half* __restrict__ B,
    const float* __restrict__ bias, const float* __restrict__ bias2,
    const float* __restrict__ extra,
    float* __restrict__ C, int K, int lda, int ldb, int ldc, int ldx,
    long sA, long sB, long sC, long sX, int mode, float alpha, int causal)
{
    __shared__ __half As[2][128*LDH];
    __shared__ __half Bs[2][128*LDH];
    const int tid = threadIdx.x, lane = tid&31, wid = tid>>5;
    const int m0 = blockIdx.y*128, n0 = blockIdx.x*128;
    A += (long)blockIdx.z*sA; B += (long)blockIdx.z*sB; C += (long)blockIdx.z*sC;
    if (extra) extra += (long)blockIdx.z*sX;

    if (mode==1 && causal && n0 > m0){
        for (int idx = tid; idx < 128*32; idx += 256){
            int r = idx>>5, c4 = (idx&31)*4;
            *(float4*)(C + (long)(m0+r)*ldc + n0+c4) =
                *(const float4*)(extra + (long)(m0+r)*ldx + n0+c4);
        }
        return;
    }
    const int Keff = (mode==2 && causal && m0+128 < K) ? m0+128 : K;

    const int g = lane>>2, tig = lane&3;
    const int wm = wid&3, wn = wid>>2;
    const int lrow = tid>>1, lseg = tid&1;

    uint32_t dA[2], dB[2];
    dA[0] = s2u(&As[0][lrow*LDH + lseg*16]);
    dA[1] = s2u(&As[1][lrow*LDH + lseg*16]);
    dB[0] = s2u(&Bs[0][lrow*LDH + lseg*16]);
    dB[1] = s2u(&Bs[1][lrow*LDH + lseg*16]);
    const __half* srcA = A + (long)(m0+lrow)*lda + lseg*16;
    const __half* srcB = B + (long)(n0+lrow)*ldb + lseg*16;

    const int ar = wm*32 + (lane&15), ac = (lane>>4)<<3;
    const int br = wn*64 + (lane&7) + ((lane>>4)<<3), bc = ((lane>>3)&1)<<3;
    uint32_t aAd[2][2], bAd[2][4];
    #pragma unroll
    for (int bb=0;bb<2;bb++){
        #pragma unroll
        for (int mt=0;mt<2;mt++) aAd[bb][mt] = s2u(&As[bb][(ar+mt*16)*LDH + ac]);
        #pragma unroll
        for (int p=0;p<4;p++)    bAd[bb][p]  = s2u(&Bs[bb][(br+p*16)*LDH + bc]);
    }

    float c[2][8][4];
    #pragma unroll
    for (int mt=0;mt<2;mt++)
        #pragma unroll
        for (int nt=0;nt<8;nt++)
            #pragma unroll
            for (int i=0;i<4;i++) c[mt][nt][i]=0.f;

    const int ntile = Keff/32;
    CP_A16(dA[0],    srcA);      CP_A16(dA[0]+16, srcA+8);
    CP_A16(dB[0],    srcB);      CP_A16(dB[0]+16, srcB+8);
    CP_COMMIT();

    for (int ch=0; ch<ntile; ch++){
        const int buf = ch&1;
        if (ch+1 < ntile){
            const int k1 = (ch+1)*32, b1 = (ch+1)&1;
            CP_A16(dA[b1],    srcA+k1);   CP_A16(dA[b1]+16, srcA+k1+8);
            CP_A16(dB[b1],    srcB+k1);   CP_A16(dB[b1]+16, srcB+k1+8);
            CP_COMMIT();
            CP_WAIT1();
        } else {
            CP_WAIT0();
        }
        __syncthreads();

        #pragma unroll
        for (int kk=0; kk<2; kk++){
            const uint32_t ko = kk*32;
            uint32_t a[2][4], b[4][4];
            #pragma unroll
            for (int mt=0;mt<2;mt++)
                LDSM_X4(a[mt][0],a[mt][1],a[mt][2],a[mt][3], aAd[buf][mt]+ko);
            #pragma unroll
            for (int p=0;p<4;p++)
                LDSM_X4(b[p][0],b[p][1],b[p][2],b[p][3], bAd[buf][p]+ko);
            #pragma unroll
            for (int mt=0;mt<2;mt++)
                #pragma unroll
                for (int nt=0;nt<8;nt++){
                    const int p = nt>>1, o = (nt&1)*2;
                    MMA_F16(c[mt][nt], a[mt], b[p][o], b[p][o+1]);
                }
        }
        __syncthreads();
    }

    #pragma unroll
    for (int mt=0;mt<2;mt++){
        long r0 = m0 + wm*32 + mt*16 + g;
        long r1 = r0 + 8;
        #pragma unroll
        for (int nt=0;nt<8;nt++){
            long n = n0 + wn*64 + nt*8 + 2*tig;
            float v0=c[mt][nt][0]*alpha, v1=c[mt][nt][1]*alpha;
            float v2=c[mt][nt][2]*alpha, v3=c[mt][nt][3]*alpha;
            if (mode==0 || mode==3){
                float b0=bias[n], b1=bias[n+1];
                if (bias2){ b0+=bias2[n]; b1+=bias2[n+1]; }
                v0+=b0; v1+=b1; v2+=b0; v3+=b1;
            }
            if (mode==3){
                v0 = v0*fsigm(1.702f*v0); v1 = v1*fsigm(1.702f*v1);
                v2 = v2*fsigm(1.702f*v2); v3 = v3*fsigm(1.702f*v3);
            }
            if (mode==1 || mode==2 || mode==3){
                v0 += extra[r0*ldx+n]; v1 += extra[r0*ldx+n+1];
                v2 += extra[r1*ldx+n]; v3 += extra[r1*ldx+n+1];
            }
            float2 lo = {v0,v1}, hi = {v2,v3};
            *(float2*)(C + r0*ldc + n) = lo;
            *(float2*)(C + r1*ldc + n) = hi;
        }
    }
}

/* ---------------- f32 -> f16 convert (16B vectorized) -------------------------- */
struct H2x4 { __half2 a, b, c, d; };
__global__ void __launch_bounds__(256) cvt_h_k(const float* __restrict__ in,
                                               __half* __restrict__ out, long n){
    for (long i = ((long)blockIdx.x*blockDim.x + threadIdx.x)*8; i < n;
         i += (long)gridDim.x*blockDim.x*8){
        float4 a = *(const float4*)(in+i);
        float4 b = *(const float4*)(in+i+4);
        H2x4 o;
        o.a = __floats2half2_rn(a.x,a.y);
        o.b = __floats2half2_rn(a.z,a.w);
        o.c = __floats2half2_rn(b.x,b.y);
        o.d = __floats2half2_rn(b.z,b.w);
        *(H2x4*)(out+i) = o;
    }
}

/* ---------------- LayerNorm over last dim (E=1024), one block per row ---------- */
__global__ void __launch_bounds__(256) ln_kernel(const float* __restrict__ in,
                                                 float* __restrict__ out,
                                                 const float* __restrict__ gamma,
                                                 const float* __restrict__ beta)
{
    long row = blockIdx.x;
    const float4* x = (const float4*)(in + row*E_);
    int t = threadIdx.x;
    float4 v = x[t];
    float s = v.x+v.y+v.z+v.w;
    float q = v.x*v.x+v.y*v.y+v.z*v.z+v.w*v.w;
    #pragma unroll
    for (int o=16;o;o>>=1){ s += __shfl_xor_sync(~0u,s,o); q += __shfl_xor_sync(~0u,q,o); }
    __shared__ float ss[8], sq[8];
    int w = t>>5, l = t&31;
    if (l==0){ ss[w]=s; sq[w]=q; }
    __syncthreads();
    if (t<32){
        float a = (l<8)? ss[l]:0.f, b = (l<8)? sq[l]:0.f;
        #pragma unroll
        for (int o=4;o;o>>=1){ a += __shfl_xor_sync(~0u,a,o); b += __shfl_xor_sync(~0u,b,o); }
        if (l==0){ ss[0]=a; sq[0]=b; }
    }
    __syncthreads();
    float mean = ss[0]*(1.0f/E_);
    float var  = sq[0]*(1.0f/E_) - mean*mean;
    float inv  = rsqrtf(fmaxf(var,0.f)+1e-12f);
    float4 g = ((const float4*)gamma)[t];
    float4 b = ((const float4*)beta)[t];
    float4 o;
    o.x=(v.x-mean)*inv*g.x+b.x; o.y=(v.y-mean)*inv*g.y+b.y;
    o.z=(v.z-mean)*inv*g.z+b.z; o.w=(v.w-mean)*inv*g.w+b.w;
    ((float4*)(out + row*E_))[t] = o;
}

/* ---------------- small prep kernels ------------------------------------------ */
__global__ void __launch_bounds__(256) vs_proj_k(const float* __restrict__ vs_p,
                                                 const float* __restrict__ op_W,
                                                 const float* __restrict__ op_b){
    int j = blockIdx.x*8 + (threadIdx.x>>5);
    int l = threadIdx.x & 31;
    const float* w = op_W + (long)j*E_;
    float acc = 0.f;
    for (int k=l; k<E_; k+=32) acc += psigm(vs_p[k]) * w[k];
    #pragma unroll
    for (int o=16;o;o>>=1) acc += __shfl_xor_sync(~0u,acc,o);
    if (l==0) g_tbuf[j] = acc + op_b[j];
}
__global__ void vs_gate_k(){
    int e = blockIdx.x*256 + threadIdx.x;
    if (e < E_) g_vsgv[e] = psigm(g_tbuf[E_+e]) * tanhf(g_tbuf[e]);
}
__global__ void zero_state_k(){
    int i = blockIdx.x*256 + threadIdx.x;
    if (i < B_*E_){ g_hbuf[0][i] = 0.f; g_hbuf[1][i] = 0.f; }
}
/* q = sigm(qs)*query ; k = sigm(ks)*mh  -> half outputs */
__global__ void scale_qkv_k(const float* __restrict__ qs, const float* __restrict__ ks){
    for (long i = (long)blockIdx.x*blockDim.x + threadIdx.x; i < (long)SB_*E_;
         i += (long)gridDim.x*blockDim.x){
        int e = (int)(i & (E_-1));
        gh_qsc[i] = __float2half(fsigm(qs[e]) * g_query[i]);
        gh_ksc[i] = __float2half(fsigm(ks[e]) * g_mh[i]);
    }
}
/* vT[b][e][s] = vsgv[e] * mh[s][b][e] -> half, tiled transpose */
__global__ void __launch_bounds__(256) vT_k(){
    __shared__ float Ts[32][33];
    const int b = blockIdx.z, s0 = blockIdx.x*32, e0 = blockIdx.y*32;
    const int tx = threadIdx.x & 31, ty = threadIdx.x >> 5;
    #pragma unroll
    for (int i=0;i<4;i++){
        int sl = ty*4+i;
        Ts[sl][tx] = g_mh[((long)(s0+sl)*B_ + b)*E_ + e0+tx];
    }
    __syncthreads();
    #pragma unroll
    for (int i=0;i<4;i++){
        int el = ty*4+i;
        gh_vT[((long)b*E_ + e0+el)*S_ + s0+tx] = __float2half(Ts[tx][el] * g_vsgv[e0+el]);
    }
}

/* ---------------- persistent LSTM: 128 blocks x 256 threads -------------------- */
#define LSTM_BLOCKS 128
#define LSTM_SMEM_BYTES (131072 + 32768 + 8192 + 1024 + 256)

__device__ __forceinline__ void fma2(unsigned long long &acc,
                                     unsigned long long a, unsigned long long b){
    asm("fma.rn.f32x2 %0, %1, %2, %0;" : "+l"(acc) : "l"(a), "l"(b));
}
__device__ __forceinline__ float f2sum(unsigned long long v){
    return __uint_as_float((unsigned)v) + __uint_as_float((unsigned)(v>>32));
}

__global__ void __launch_bounds__(256) lstm_persist_k(const float* __restrict__ gx,
                                                      const float* __restrict__ Whh,
                                                      float* __restrict__ rnn)
{
    extern __shared__ float sm[];
    float* w_sm    = sm;
    float* h_sm    = sm + 32768;
    float* red_sm  = h_sm + 8192;
    float* gate_sm = red_sm + 2048;

    const int tid = threadIdx.x;
    const int e_base = blockIdx.x*8;
    const int s_w = tid>>5;
    const int r   = tid&31;

    for (int rr = 0; rr < 32; rr++){
        long j = (long)((rr>>3)*E_ + e_base + (rr&7));
        const float4* src = (const float4*)(Whh + j*E_);
        for (int k4 = tid; k4 < 256; k4 += 256)
            *(float4*)&w_sm[(k4*32 + rr)*4] = src[k4];
    }

    float c_reg = 0.f;
    const int cb = tid>>3, ce = tid&7;
    /* gx prefetch mapping (same thread does the reduce) */
    const int b2 = tid>>5, rr2 = tid&31;
    const long j2 = (long)((rr2>>3)*E_ + e_base + (rr2&7));
    const float* gx_p = gx + (long)b2*G4_ + j2;

    unsigned* pcnt = &g_bar_cnt;
    unsigned* pgen = &g_bar_gen;

    __syncthreads();

    int parity = 0;
    for (int step = 0; step < S_; step++){
        /* prefetch this step's gx early (DRAM latency hidden behind h+compute) */
        float gpref = __ldg(gx_p + (long)step*B_*G4_);

        const float4* hsrc = (const float4*)g_hbuf[parity];
        #pragma unroll
        for (int i = tid; i < 2048; i += 256)
            *(float4*)&h_sm[i*4] = __ldcg(hsrc + i);
        __syncthreads();

        unsigned long long acc0[8], acc1[8];
        #pragma unroll
        for (int b=0;b<8;b++){ acc0[b]=0ull; acc1[b]=0ull; }
        const int k4b = s_w*32;
        #pragma unroll 8
        for (int k4 = k4b; k4 < k4b+32; k4++){
            const unsigned long long* w2 = (const unsigned long long*)&w_sm[(k4*32 + r)*4];
            unsigned long long w01 = w2[0], w23 = w2[1];
            #pragma unroll
            for (int b=0;b<8;b++){
                const unsigned long long* h2p = (const unsigned long long*)&h_sm[b*E_ + k4*4];
                fma2(acc0[b], w01, h2p[0]);
                fma2(acc1[b], w23, h2p[1]);
            }
        }
        #pragma unroll
        for (int b=0;b<8;b++)
            red_sm[s_w*256 + r*8 + b] = f2sum(acc0[b]) + f2sum(acc1[b]);
        __syncthreads();

        {
            float g = gpref;
            #pragma unroll
            for (int ss=0; ss<8; ss++) g += red_sm[ss*256 + rr2*8 + b2];
            gate_sm[rr2*8 + b2] = g;
        }
        __syncthreads();

        if (tid < 64){
            float gi = gate_sm[(0*8+ce)*8 + cb];
            float gf = gate_sm[(1*8+ce)*8 + cb];
            float gg = gate_sm[(2*8+ce)*8 + cb];
            float go = gate_sm[(3*8+ce)*8 + cb];
            c_reg = psigm(gf)*c_reg + psigm(gi)*tanhf(gg);
            float h = psigm(go)*tanhf(c_reg);
            int idx = cb*E_ + e_base + ce;
            __stcg(&g_hbuf[parity^1][idx], h);
            rnn[(long)step*B_*E_ + idx] = h;
        }
        __syncthreads();

        /* grid barrier: release-arrive + acquire-spin (graph-replay-safe gen counter) */
        if (tid == 0){
            unsigned gen;
            asm volatile("ld.relaxed.gpu.u32 %0, [%1];" : "=r"(gen) : "l"(pgen));
            unsigned prev;
            asm volatile("atom.release.gpu.add.u32 %0, [%1], 1;"
                         : "=r"(prev) : "l"(pcnt) : "memory");
            if (prev == LSTM_BLOCKS - 1u){
                asm volatile("st.relaxed.gpu.u32 [%0], 0;" :: "l"(pcnt) : "memory");
                asm volatile("st.release.gpu.u32 [%0], %1;" :: "l"(pgen), "r"(gen+1u) : "memory");
            } else {
                unsigned cur;
                do {
                    asm volatile("ld.acquire.gpu.u32 %0, [%1];" : "=r"(cur) : "l"(pgen) : "memory");
                } while (cur == gen);
            }
        }
        __syncthreads();
        parity ^= 1;
    }
}

/* ---------------- softmax over rows of length S, writes half ------------------- */
__global__ void __launch_bounds__(256) softmax_k(const float* __restrict__ sc,
                                                 __half* __restrict__ outh){
    const float* p = sc + (long)blockIdx.x*S_;
    __half* po = outh + (long)blockIdx.x*S_;
    int t = threadIdx.x;
    float4 v0 = ((const float4*)p)[t], v1 = ((const float4*)p)[t+256];
    float mx = fmaxf(fmaxf(fmaxf(v0.x,v0.y),fmaxf(v0.z,v0.w)),
                     fmaxf(fmaxf(v1.x,v1.y),fmaxf(v1.z,v1.w)));
    #pragma unroll
    for (int o=16;o;o>>=1) mx = fmaxf(mx, __shfl_xor_sync(~0u,mx,o));
    __shared__ float sm[8];
    int w=t>>5, l=t&31;
    if (l==0) sm[w]=mx;
    __syncthreads();
    if (t<32){ float a=(l<8)?sm[l]:-1e30f;
        #pragma unroll
        for(int o=4;o;o>>=1) a=fmaxf(a,__shfl_xor_sync(~0u,a,o));
        if(l==0) sm[0]=a; }
    __syncthreads();
    mx = sm[0];
    v0.x=__expf(v0.x-mx); v0.y=__expf(v0.y-mx); v0.z=__expf(v0.z-mx); v0.w=__expf(v0.w-mx);
    v1.x=__expf(v1.x-mx); v1.y=__expf(v1.y-mx); v1.z=__expf(v1.z-mx); v1.w=__expf(v1.w-mx);
    float s = v0.x+v0.y+v0.z+v0.w+v1.x+v1.y+v1.z+v1.w;
    #pragma unroll
    for (int o=16;o;o>>=1) s += __shfl_xor_sync(~0u,s,o);
    __shared__ float s2[8];
    if (l==0) s2[w]=s;
    __syncthreads();
    if (t<32){ float a=(l<8)?s2[l]:0.f;
        #pragma unroll
        for(int o=4;o;o>>=1) a+=__shfl_xor_sync(~0u,a,o);
        if(l==0) s2[0]=a; }
    __syncthreads();
    float inv = 1.0f/s2[0];
    __half2 h0 = __floats2half2_rn(v0.x*inv, v0.y*inv);
    __half2 h1 = __floats2half2_rn(v0.z*inv, v0.w*inv);
    __half2 h2 = __floats2half2_rn(v1.x*inv, v1.y*inv);
    __half2 h3 = __floats2half2_rn(v1.z*inv, v1.w*inv);
    ((__half2*)po)[2*t]     = h0;
    ((__half2*)po)[2*t+1]   = h1;
    ((__half2*)po)[2*(t+256)]   = h2;
    ((__half2*)po)[2*(t+256)+1] = h3;
}

/* ---------------- host side ---------------------------------------------------- */
static float* devp(const void* sym){ void* p=0; cudaGetSymbolAddress(&p,sym); return (float*)p; }
static __half* devph(const void* sym){ void* p=0; cudaGetSymbolAddress(&p,sym); return (__half*)p; }

extern "C" void kernel_launch(void* const* d_in, const int* in_sizes, int n_in,
                              void* d_out, int out_size)
{
    const float* inputs = (const float*)d_in[0];
    const float* mask   = (const float*)d_in[1];
    const float* Wih    = (const float*)d_in[3];
    const float* Whh    = (const float*)d_in[4];
    const float* bih    = (const float*)d_in[5];
    const float* bhh    = (const float*)d_in[6];
    const float* lnstart_g=(const float*)d_in[7],  *lnstart_b=(const float*)d_in[8];
    const float* lnmem_g  =(const float*)d_in[9],  *lnmem_b  =(const float*)d_in[10];
    const float* lnmid_g  =(const float*)d_in[11], *lnmid_b  =(const float*)d_in[12];
    const float* lnff_g   =(const float*)d_in[13], *lnff_b   =(const float*)d_in[14];
    const float* lnxff_g  =(const float*)d_in[15], *lnxff_b  =(const float*)d_in[16];
    const float* qln_g    =(const float*)d_in[17], *qln_b    =(const float*)d_in[18];
    const float* qs    = (const float*)d_in[19];
    const float* ks_p  = (const float*)d_in[20];
    const float* vs_p  = (const float*)d_in[21];
    const float* op_W  = (const float*)d_in[22];
    const float* op_b  = (const float*)d_in[23];
    const float* ql_W  = (const float*)d_in[24];
    const float* ql_b  = (const float*)d_in[25];
    const float* boom_W= (const float*)d_in[26];
    const float* boom_b= (const float*)d_in[27];
    float* out = (float*)d_out;

    float *xln=devp(g_xln), *gx=devp(g_gx), *rnn=devp(g_rnn), *mh=devp(g_mh),
          *hmid=devp(g_hmid), *qpre=devp(g_qpre), *query=devp(g_query),
          *scores=devp(g_scores), *h2=devp(g_h2), *xff=devp(g_xff),
          *lnffo=devp(g_lnffo);
    __half *hxln=devph(gh_xln), *hWih=devph(gh_Wih), *hhmid=devph(gh_hmid),
           *hqlW=devph(gh_qlW), *hqsc=devph(gh_qsc), *hksc=devph(gh_ksc),
           *hvT=devph(gh_vT), *hsc=devph(gh_sc), *hxff=devph(gh_xff),
           *hbmW=devph(gh_bmW);

    cudaFuncSetAttribute(lstm_persist_k,
                         cudaFuncAttributeMaxDynamicSharedMemorySize, LSTM_SMEM_BYTES);

    /* launch order: #4 is the gx GEMM (observed ncu capture = my 4th launch) */
    ln_kernel<<<SB_,256>>>(inputs, xln, lnstart_g, lnstart_b);     /* 1 */
    cvt_h_k<<<2048,256>>>(xln,  hxln, (long)SB_*E_);               /* 2 */
    cvt_h_k<<<2048,256>>>(Wih,  hWih, (long)G4_*E_);               /* 3 */

    /* gx = xln @ Wih^T + bih + bhh : fp16 mma */
    gemm_h<<<dim3(32,128,1),256>>>(hxln,hWih,bih,bhh,0, gx,        /* 4 */
        E_, E_,E_,G4_,0, 0,0,0,0, 0, 1.0f, 0);

    vs_proj_k<<<256,256>>>(vs_p,op_W,op_b);
    vs_gate_k<<<4,256>>>();
    zero_state_k<<<32,256>>>();

    lstm_persist_k<<<LSTM_BLOCKS,256,LSTM_SMEM_BYTES>>>(gx, Whh, rnn);

    ln_kernel<<<SB_,256>>>(rnn, mh,   lnmem_g, lnmem_b);
    ln_kernel<<<SB_,256>>>(rnn, hmid, lnmid_g, lnmid_b);
    cvt_h_k<<<2048,256>>>(hmid, hhmid, (long)SB_*E_);
    cvt_h_k<<<512,256>>>(ql_W,  hqlW, (long)E_*E_);
    cvt_h_k<<<512,256>>>(boom_W, hbmW, (long)E_*E_);

    /* query projection */
    gemm_h<<<dim3(8,128,1),256>>>(hhmid,hqlW,ql_b,0,0, qpre,
        E_, E_,E_,E_,0, 0,0,0,0, 0, 1.0f, 0);
    ln_kernel<<<SB_,256>>>(qpre, query, qln_g, qln_b);
    scale_qkv_k<<<1024,256>>>(qs, ks_p);
    vT_k<<<dim3(S_/32,E_/32,B_),256>>>();

    /* scores = q.k/sqrt(E) + mask : batched NT, causal-skip */
    gemm_h<<<dim3(16,16,8),256>>>(hqsc,hksc,0,0,mask, scores,
        E_, B_*E_, B_*E_, S_, S_, E_, E_, (long)S_*S_, 0, 1, 0.03125f, 1);

    /* softmax: float in, half out (fused cvt) */
    softmax_k<<<B_*S_,256>>>(scores, hsc);

    /* mix = w @ vT^T + hmid : batched NT, causal K-limit */
    gemm_h<<<dim3(8,16,8),256>>>(hsc,hvT,0,0,hmid, h2,
        S_, S_, S_, B_*E_, B_*E_, (long)S_*S_, (long)E_*S_, E_, E_, 2, 1.0f, 1);

    /* boom */
    ln_kernel<<<SB_,256>>>(h2, xff,   lnxff_g, lnxff_b);
    ln_kernel<<<SB_,256>>>(h2, lnffo, lnff_g,  lnff_b);
    cvt_h_k<<<2048,256>>>(xff, hxff, (long)SB_*E_);
    gemm_h<<<dim3(8,128,1),256>>>(hxff,hbmW,boom_b,0,lnffo, out,
        E_, E_,E_,E_,E_, 0,0,0,0, 3, 1.0f, 0);
}

// round 13
// speedup vs baseline: 1.5049x; 1.5049x over previous
#include <cuda_runtime.h>
#include <cuda_fp16.h>
#include <math.h>
#include <cstdint>

#define S_  2048
#define B_  8
#define E_  1024
#define SB_ (S_*B_)
#define G4_ (4*E_)

/* ---------------- static device scratch (no runtime allocation) ---------------- */
__device__ float g_xln  [SB_*E_];
__device__ float g_gx   [(size_t)SB_*G4_];
__device__ float g_rnn  [SB_*E_];
__device__ float g_mh   [SB_*E_];
__device__ float g_hmid [SB_*E_];
__device__ float g_qpre [SB_*E_];
__device__ float g_query[SB_*E_];
__device__ float g_scores[(size_t)B_*S_*S_];
__device__ float g_h2   [SB_*E_];
__device__ float g_xff  [SB_*E_];
__device__ float g_lnffo[SB_*E_];
__device__ float g_tbuf [2*E_];
__device__ float g_vsgv [E_];
__device__ float g_hbuf [2][B_*E_];
__device__ unsigned g_flags[128*32];    /* one padded flag line per LSTM block */

/* fp16 mirrors for tensor-core GEMM inputs */
__device__ __half gh_xln [SB_*E_];
__device__ __half gh_Wih [(size_t)G4_*E_];
__device__ __half gh_hmid[SB_*E_];
__device__ __half gh_qlW [(size_t)E_*E_];
__device__ __half gh_qsc [SB_*E_];
__device__ __half gh_ksc [SB_*E_];
__device__ __half gh_vT  [(size_t)B_*E_*S_];
__device__ __half gh_sc  [(size_t)B_*S_*S_];
__device__ __half gh_xff [SB_*E_];
__device__ __half gh_bmW [(size_t)E_*E_];

__device__ __forceinline__ float fsigm(float x){ return 1.0f/(1.0f+__expf(-x)); }
__device__ __forceinline__ float psigm(float x){ return 1.0f/(1.0f+expf(-x)); }
__device__ __forceinline__ uint32_t s2u(const void* p){
    return (uint32_t)__cvta_generic_to_shared(p);
}
#define CP_A16(dst, src) \
    asm volatile("cp.async.cg.shared.global [%0], [%1], 16;" :: "r"(dst), "l"(src))
#define CP_COMMIT() asm volatile("cp.async.commit_group;" ::: "memory")
#define CP_WAIT1()  asm volatile("cp.async.wait_group 1;" ::: "memory")
#define CP_WAIT0()  asm volatile("cp.async.wait_group 0;" ::: "memory")
#define LDSM_X4(r0,r1,r2,r3,addr) \
    asm volatile("ldmatrix.sync.aligned.m8n8.x4.shared.b16 {%0,%1,%2,%3}, [%4];" \
        : "=r"(r0), "=r"(r1), "=r"(r2), "=r"(r3) : "r"(addr))
#define MMA_F16(c, a, b0, b1) \
    asm volatile("mma.sync.aligned.m16n8k16.row.col.f32.f16.f16.f32 " \
        "{%0,%1,%2,%3}, {%4,%5,%6,%7}, {%8,%9}, {%0,%1,%2,%3};" \
        : "+f"((c)[0]), "+f"((c)[1]), "+f"((c)[2]), "+f"((c)[3]) \
        : "r"((a)[0]), "r"((a)[1]), "r"((a)[2]), "r"((a)[3]), "r"(b0), "r"(b1))

/* ---------------- fp16 tensor-core GEMM 128x128, K-tile 32, cp.async x2 -------- */
#define LDH 40
__global__ void __launch_bounds__(256) gemm_h(
    const __half* __restrict__ A, const __half* __restrict__ B,
    const float* __restrict__ bias, const float* __restrict__ bias2,
    const float* __restrict__ extra,
    float* __restrict__ C, int K, int lda, int ldb, int ldc, int ldx,
    long sA, long sB, long sC, long sX, int mode, float alpha, int causal)
{
    __shared__ __half As[2][128*LDH];
    __shared__ __half Bs[2][128*LDH];
    const int tid = threadIdx.x, lane = tid&31, wid = tid>>5;
    const int m0 = blockIdx.y*128, n0 = blockIdx.x*128;
    A += (long)blockIdx.z*sA; B += (long)blockIdx.z*sB; C += (long)blockIdx.z*sC;
    if (extra) extra += (long)blockIdx.z*sX;

    if (mode==1 && causal && n0 > m0){
        for (int idx = tid; idx < 128*32; idx += 256){
            int r = idx>>5, c4 = (idx&31)*4;
            *(float4*)(C + (long)(m0+r)*ldc + n0+c4) =
                *(const float4*)(extra + (long)(m0+r)*ldx + n0+c4);
        }
        return;
    }
    const int Keff = (mode==2 && causal && m0+128 < K) ? m0+128 : K;

    const int g = lane>>2, tig = lane&3;
    const int wm = wid&3, wn = wid>>2;
    const int lrow = tid>>1, lseg = tid&1;

    uint32_t dA[2], dB[2];
    dA[0] = s2u(&As[0][lrow*LDH + lseg*16]);
    dA[1] = s2u(&As[1][lrow*LDH + lseg*16]);
    dB[0] = s2u(&Bs[0][lrow*LDH + lseg*16]);
    dB[1] = s2u(&Bs[1][lrow*LDH + lseg*16]);
    const __half* srcA = A + (long)(m0+lrow)*lda + lseg*16;
    const __half* srcB = B + (long)(n0+lrow)*ldb + lseg*16;

    const int ar = wm*32 + (lane&15), ac = (lane>>4)<<3;
    const int br = wn*64 + (lane&7) + ((lane>>4)<<3), bc = ((lane>>3)&1)<<3;
    uint32_t aAd[2][2], bAd[2][4];
    #pragma unroll
    for (int bb=0;bb<2;bb++){
        #pragma unroll
        for (int mt=0;mt<2;mt++) aAd[bb][mt] = s2u(&As[bb][(ar+mt*16)*LDH + ac]);
        #pragma unroll
        for (int p=0;p<4;p++)    bAd[bb][p]  = s2u(&Bs[bb][(br+p*16)*LDH + bc]);
    }

    float c[2][8][4];
    #pragma unroll
    for (int mt=0;mt<2;mt++)
        #pragma unroll
        for (int nt=0;nt<8;nt++)
            #pragma unroll
            for (int i=0;i<4;i++) c[mt][nt][i]=0.f;

    const int ntile = Keff/32;
    CP_A16(dA[0],    srcA);      CP_A16(dA[0]+16, srcA+8);
    CP_A16(dB[0],    srcB);      CP_A16(dB[0]+16, srcB+8);
    CP_COMMIT();

    for (int ch=0; ch<ntile; ch++){
        const int buf = ch&1;
        if (ch+1 < ntile){
            const int k1 = (ch+1)*32, b1 = (ch+1)&1;
            CP_A16(dA[b1],    srcA+k1);   CP_A16(dA[b1]+16, srcA+k1+8);
            CP_A16(dB[b1],    srcB+k1);   CP_A16(dB[b1]+16, srcB+k1+8);
            CP_COMMIT();
            CP_WAIT1();
        } else {
            CP_WAIT0();
        }
        __syncthreads();

        #pragma unroll
        for (int kk=0; kk<2; kk++){
            const uint32_t ko = kk*32;
            uint32_t a[2][4], b[4][4];
            #pragma unroll
            for (int mt=0;mt<2;mt++)
                LDSM_X4(a[mt][0],a[mt][1],a[mt][2],a[mt][3], aAd[buf][mt]+ko);
            #pragma unroll
            for (int p=0;p<4;p++)
                LDSM_X4(b[p][0],b[p][1],b[p][2],b[p][3], bAd[buf][p]+ko);
            #pragma unroll
            for (int mt=0;mt<2;mt++)
                #pragma unroll
                for (int nt=0;nt<8;nt++){
                    const int p = nt>>1, o = (nt&1)*2;
                    MMA_F16(c[mt][nt], a[mt], b[p][o], b[p][o+1]);
                }
        }
        __syncthreads();
    }

    #pragma unroll
    for (int mt=0;mt<2;mt++){
        long r0 = m0 + wm*32 + mt*16 + g;
        long r1 = r0 + 8;
        #pragma unroll
        for (int nt=0;nt<8;nt++){
            long n = n0 + wn*64 + nt*8 + 2*tig;
            float v0=c[mt][nt][0]*alpha, v1=c[mt][nt][1]*alpha;
            float v2=c[mt][nt][2]*alpha, v3=c[mt][nt][3]*alpha;
            if (mode==0 || mode==3){
                float b0=bias[n], b1=bias[n+1];
                if (bias2){ b0+=bias2[n]; b1+=bias2[n+1]; }
                v0+=b0; v1+=b1; v2+=b0; v3+=b1;
            }
            if (mode==3){
                v0 = v0*fsigm(1.702f*v0); v1 = v1*fsigm(1.702f*v1);
                v2 = v2*fsigm(1.702f*v2); v3 = v3*fsigm(1.702f*v3);
            }
            if (mode==1 || mode==2 || mode==3){
                v0 += extra[r0*ldx+n]; v1 += extra[r0*ldx+n+1];
                v2 += extra[r1*ldx+n]; v3 += extra[r1*ldx+n+1];
            }
            float2 lo = {v0,v1}, hi = {v2,v3};
            *(float2*)(C + r0*ldc + n) = lo;
            *(float2*)(C + r1*ldc + n) = hi;
        }
    }
}

/* ---------------- f32 -> f16 convert (16B vectorized) -------------------------- */
struct H2x4 { __half2 a, b, c, d; };
__global__ void __launch_bounds__(256) cvt_h_k(const float* __restrict__ in,
                                               __half* __restrict__ out, long n){
    for (long i = ((long)blockIdx.x*blockDim.x + threadIdx.x)*8; i < n;
         i += (long)gridDim.x*blockDim.x*8){
        float4 a = *(const float4*)(in+i);
        float4 b = *(const float4*)(in+i+4);
        H2x4 o;
        o.a = __floats2half2_rn(a.x,a.y);
        o.b = __floats2half2_rn(a.z,a.w);
        o.c = __floats2half2_rn(b.x,b.y);
        o.d = __floats2half2_rn(b.z,b.w);
        *(H2x4*)(out+i) = o;
    }
}

/* ---------------- LayerNorm over last dim (E=1024), one block per row ---------- */
__global__ void __launch_bounds__(256) ln_kernel(const float* __restrict__ in,
                                                 float* __restrict__ out,
                                                 const float* __restrict__ gamma,
                                                 const float* __restrict__ beta)
{
    long row = blockIdx.x;
    const float4* x = (const float4*)(in + row*E_);
    int t = threadIdx.x;
    float4 v = x[t];
    float s = v.x+v.y+v.z+v.w;
    float q = v.x*v.x+v.y*v.y+v.z*v.z+v.w*v.w;
    #pragma unroll
    for (int o=16;o;o>>=1){ s += __shfl_xor_sync(~0u,s,o); q += __shfl_xor_sync(~0u,q,o); }
    __shared__ float ss[8], sq[8];
    int w = t>>5, l = t&31;
    if (l==0){ ss[w]=s; sq[w]=q; }
    __syncthreads();
    if (t<32){
        float a = (l<8)? ss[l]:0.f, b = (l<8)? sq[l]:0.f;
        #pragma unroll
        for (int o=4;o;o>>=1){ a += __shfl_xor_sync(~0u,a,o); b += __shfl_xor_sync(~0u,b,o); }
        if (l==0){ ss[0]=a; sq[0]=b; }
    }
    __syncthreads();
    float mean = ss[0]*(1.0f/E_);
    float var  = sq[0]*(1.0f/E_) - mean*mean;
    float inv  = rsqrtf(fmaxf(var,0.f)+1e-12f);
    float4 g = ((const float4*)gamma)[t];
    float4 b = ((const float4*)beta)[t];
    float4 o;
    o.x=(v.x-mean)*inv*g.x+b.x; o.y=(v.y-mean)*inv*g.y+b.y;
    o.z=(v.z-mean)*inv*g.z+b.z; o.w=(v.w-mean)*inv*g.w+b.w;
    ((float4*)(out + row*E_))[t] = o;
}

/* ---------------- small prep kernels ------------------------------------------ */
__global__ void __launch_bounds__(256) vs_proj_k(const float* __restrict__ vs_p,
                                                 const float* __restrict__ op_W,
                                                 const float* __restrict__ op_b){
    int j = blockIdx.x*8 + (threadIdx.x>>5);
    int l = threadIdx.x & 31;
    const float* w = op_W + (long)j*E_;
    float acc = 0.f;
    for (int k=l; k<E_; k+=32) acc += psigm(vs_p[k]) * w[k];
    #pragma unroll
    for (int o=16;o;o>>=1) acc += __shfl_xor_sync(~0u,acc,o);
    if (l==0) g_tbuf[j] = acc + op_b[j];
}
__global__ void vs_gate_k(){
    int e = blockIdx.x*256 + threadIdx.x;
    if (e < E_) g_vsgv[e] = psigm(g_tbuf[E_+e]) * tanhf(g_tbuf[e]);
}
__global__ void zero_state_k(){
    int i = blockIdx.x*256 + threadIdx.x;
    if (i < B_*E_){ g_hbuf[0][i] = 0.f; g_hbuf[1][i] = 0.f; }
    if (i < 128*32) g_flags[i] = 0u;
}
__global__ void scale_qkv_k(const float* __restrict__ qs, const float* __restrict__ ks){
    for (long i = (long)blockIdx.x*blockDim.x + threadIdx.x; i < (long)SB_*E_;
         i += (long)gridDim.x*blockDim.x){
        int e = (int)(i & (E_-1));
        gh_qsc[i] = __float2half(fsigm(qs[e]) * g_query[i]);
        gh_ksc[i] = __float2half(fsigm(ks[e]) * g_mh[i]);
    }
}
__global__ void __launch_bounds__(256) vT_k(){
    __shared__ float Ts[32][33];
    const int b = blockIdx.z, s0 = blockIdx.x*32, e0 = blockIdx.y*32;
    const int tx = threadIdx.x & 31, ty = threadIdx.x >> 5;
    #pragma unroll
    for (int i=0;i<4;i++){
        int sl = ty*4+i;
        Ts[sl][tx] = g_mh[((long)(s0+sl)*B_ + b)*E_ + e0+tx];
    }
    __syncthreads();
    #pragma unroll
    for (int i=0;i<4;i++){
        int el = ty*4+i;
        gh_vT[((long)b*E_ + e0+el)*S_ + s0+tx] = __float2half(Ts[tx][el] * g_vsgv[e0+el]);
    }
}

/* ---------------- persistent LSTM: 128 blocks x 256 threads -------------------- */
#define LSTM_BLOCKS 128
#define LSTM_SMEM_BYTES (131072 + 32768 + 8192 + 1024 + 256)

__device__ __forceinline__ void fma2(unsigned long long &acc,
                                     unsigned long long a, unsigned long long b){
    asm("fma.rn.f32x2 %0, %1, %2, %0;" : "+l"(acc) : "l"(a), "l"(b));
}
__device__ __forceinline__ float f2sum(unsigned long long v){
    return __uint_as_float((unsigned)v) + __uint_as_float((unsigned)(v>>32));
}

__global__ void __launch_bounds__(256) lstm_persist_k(const float* __restrict__ gx,
                                                      const float* __restrict__ Whh,
                                                      float* __restrict__ rnn)
{
    extern __shared__ float sm[];
    float* w_sm    = sm;
    float* h_sm    = sm + 32768;
    float* red_sm  = h_sm + 8192;
    float* gate_sm = red_sm + 2048;

    const int tid = threadIdx.x;
    const int e_base = blockIdx.x*8;
    const int s_w = tid>>5;
    const int r   = tid&31;

    for (int rr = 0; rr < 32; rr++){
        long j = (long)((rr>>3)*E_ + e_base + (rr&7));
        const float4* src = (const float4*)(Whh + j*E_);
        for (int k4 = tid; k4 < 256; k4 += 256)
            *(float4*)&w_sm[(k4*32 + rr)*4] = src[k4];
    }

    float c_reg = 0.f;
    const int cb = tid>>3, ce = tid&7;
    const int b2 = tid>>5, rr2 = tid&31;
    const long j2 = (long)((rr2>>3)*E_ + e_base + (rr2&7));
    const float* gx_p = gx + (long)b2*G4_ + j2;

    unsigned* myflag   = &g_flags[blockIdx.x*32];
    unsigned* pollflag = &g_flags[(tid&127)*32];

    __syncthreads();

    int parity = 0;
    for (int step = 0; step < S_; step++){
        /* prefetch this step's gx early (DRAM latency hidden behind h+compute) */
        float gpref = __ldg(gx_p + (long)step*B_*G4_);

        const float4* hsrc = (const float4*)g_hbuf[parity];
        #pragma unroll
        for (int i = tid; i < 2048; i += 256)
            *(float4*)&h_sm[i*4] = __ldcg(hsrc + i);
        __syncthreads();

        unsigned long long acc0[8], acc1[8];
        #pragma unroll
        for (int b=0;b<8;b++){ acc0[b]=0ull; acc1[b]=0ull; }
        const int k4b = s_w*32;
        #pragma unroll 4
        for (int k4 = k4b; k4 < k4b+32; k4++){
            ulonglong2 wv = *(const ulonglong2*)&w_sm[(k4*32 + r)*4];
            #pragma unroll
            for (int b=0;b<8;b++){
                ulonglong2 hv = *(const ulonglong2*)&h_sm[b*E_ + k4*4];
                fma2(acc0[b], wv.x, hv.x);
                fma2(acc1[b], wv.y, hv.y);
            }
        }
        #pragma unroll
        for (int b=0;b<8;b++)
            red_sm[s_w*256 + r*8 + b] = f2sum(acc0[b]) + f2sum(acc1[b]);
        __syncthreads();

        {
            float g = gpref;
            #pragma unroll
            for (int ss=0; ss<8; ss++) g += red_sm[ss*256 + rr2*8 + b2];
            gate_sm[rr2*8 + b2] = g;
        }
        __syncthreads();

        if (tid < 64){
            float gi = gate_sm[(0*8+ce)*8 + cb];
            float gf = gate_sm[(1*8+ce)*8 + cb];
            float gg = gate_sm[(2*8+ce)*8 + cb];
            float go = gate_sm[(3*8+ce)*8 + cb];
            c_reg = psigm(gf)*c_reg + psigm(gi)*tanhf(gg);
            float h = psigm(go)*tanhf(c_reg);
            int idx = cb*E_ + e_base + ce;
            __stcg(&g_hbuf[parity^1][idx], h);
            rnn[(long)step*B_*E_ + idx] = h;
        }
        __syncthreads();

        /* distributed flags barrier: arrive on own line, poll one distinct line */
        const unsigned tgt = (unsigned)(step+1);
        if (tid == 0)
            asm volatile("st.release.gpu.u32 [%0], %1;" :: "l"(myflag), "r"(tgt) : "memory");
        if (tid < 128){
            unsigned cur;
            while (1){
                asm volatile("ld.acquire.gpu.u32 %0, [%1];" : "=r"(cur) : "l"(pollflag) : "memory");
                if (cur >= tgt) break;
                __nanosleep(20);
            }
        }
        __syncthreads();
        parity ^= 1;
    }
}

/* ---------------- softmax over rows of length S, writes half ------------------- */
__global__ void __launch_bounds__(256) softmax_k(const float* __restrict__ sc,
                                                 __half* __restrict__ outh){
    const float* p = sc + (long)blockIdx.x*S_;
    __half* po = outh + (long)blockIdx.x*S_;
    int t = threadIdx.x;
    float4 v0 = ((const float4*)p)[t], v1 = ((const float4*)p)[t+256];
    float mx = fmaxf(fmaxf(fmaxf(v0.x,v0.y),fmaxf(v0.z,v0.w)),
                     fmaxf(fmaxf(v1.x,v1.y),fmaxf(v1.z,v1.w)));
    #pragma unroll
    for (int o=16;o;o>>=1) mx = fmaxf(mx, __shfl_xor_sync(~0u,mx,o));
    __shared__ float sm[8];
    int w=t>>5, l=t&31;
    if (l==0) sm[w]=mx;
    __syncthreads();
    if (t<32){ float a=(l<8)?sm[l]:-1e30f;
        #pragma unroll
        for(int o=4;o;o>>=1) a=fmaxf(a,__shfl_xor_sync(~0u,a,o));
        if(l==0) sm[0]=a; }
    __syncthreads();
    mx = sm[0];
    v0.x=__expf(v0.x-mx); v0.y=__expf(v0.y-mx); v0.z=__expf(v0.z-mx); v0.w=__expf(v0.w-mx);
    v1.x=__expf(v1.x-mx); v1.y=__expf(v1.y-mx); v1.z=__expf(v1.z-mx); v1.w=__expf(v1.w-mx);
    float s = v0.x+v0.y+v0.z+v0.w+v1.x+v1.y+v1.z+v1.w;
    #pragma unroll
    for (int o=16;o;o>>=1) s += __shfl_xor_sync(~0u,s,o);
    __shared__ float s2[8];
    if (l==0) s2[w]=s;
    __syncthreads();
    if (t<32){ float a=(l<8)?s2[l]:0.f;
        #pragma unroll
        for(int o=4;o;o>>=1) a+=__shfl_xor_sync(~0u,a,o);
        if(l==0) s2[0]=a; }
    __syncthreads();
    float inv = 1.0f/s2[0];
    __half2 h0 = __floats2half2_rn(v0.x*inv, v0.y*inv);
    __half2 h1 = __floats2half2_rn(v0.z*inv, v0.w*inv);
    __half2 h2 = __floats2half2_rn(v1.x*inv, v1.y*inv);
    __half2 h3 = __floats2half2_rn(v1.z*inv, v1.w*inv);
    ((__half2*)po)[2*t]     = h0;
    ((__half2*)po)[2*t+1]   = h1;
    ((__half2*)po)[2*(t+256)]   = h2;
    ((__half2*)po)[2*(t+256)+1] = h3;
}

/* ---------------- host side ---------------------------------------------------- */
static float* devp(const void* sym){ void* p=0; cudaGetSymbolAddress(&p,sym); return (float*)p; }
static __half* devph(const void* sym){ void* p=0; cudaGetSymbolAddress(&p,sym); return (__half*)p; }

extern "C" void kernel_launch(void* const* d_in, const int* in_sizes, int n_in,
                              void* d_out, int out_size)
{
    const float* inputs = (const float*)d_in[0];
    const float* mask   = (const float*)d_in[1];
    const float* Wih    = (const float*)d_in[3];
    const float* Whh    = (const float*)d_in[4];
    const float* bih    = (const float*)d_in[5];
    const float* bhh    = (const float*)d_in[6];
    const float* lnstart_g=(const float*)d_in[7],  *lnstart_b=(const float*)d_in[8];
    const float* lnmem_g  =(const float*)d_in[9],  *lnmem_b  =(const float*)d_in[10];
    const float* lnmid_g  =(const float*)d_in[11], *lnmid_b  =(const float*)d_in[12];
    const float* lnff_g   =(const float*)d_in[13], *lnff_b   =(const float*)d_in[14];
    const float* lnxff_g  =(const float*)d_in[15], *lnxff_b  =(const float*)d_in[16];
    const float* qln_g    =(const float*)d_in[17], *qln_b    =(const float*)d_in[18];
    const float* qs    = (const float*)d_in[19];
    const float* ks_p  = (const float*)d_in[20];
    const float* vs_p  = (const float*)d_in[21];
    const float* op_W  = (const float*)d_in[22];
    const float* op_b  = (const float*)d_in[23];
    const float* ql_W  = (const float*)d_in[24];
    const float* ql_b  = (const float*)d_in[25];
    const float* boom_W= (const float*)d_in[26];
    const float* boom_b= (const float*)d_in[27];
    float* out = (float*)d_out;

    float *xln=devp(g_xln), *gx=devp(g_gx), *rnn=devp(g_rnn), *mh=devp(g_mh),
          *hmid=devp(g_hmid), *qpre=devp(g_qpre), *query=devp(g_query),
          *scores=devp(g_scores), *h2=devp(g_h2), *xff=devp(g_xff),
          *lnffo=devp(g_lnffo);
    __half *hxln=devph(gh_xln), *hWih=devph(gh_Wih), *hhmid=devph(gh_hmid),
           *hqlW=devph(gh_qlW), *hqsc=devph(gh_qsc), *hksc=devph(gh_ksc),
           *hvT=devph(gh_vT), *hsc=devph(gh_sc), *hxff=devph(gh_xff),
           *hbmW=devph(gh_bmW);

    cudaFuncSetAttribute(lstm_persist_k,
                         cudaFuncAttributeMaxDynamicSharedMemorySize, LSTM_SMEM_BYTES);

    /* launch order: #4 is the gx GEMM (ncu capture = my 4th launch) */
    ln_kernel<<<SB_,256>>>(inputs, xln, lnstart_g, lnstart_b);     /* 1 */
    cvt_h_k<<<2048,256>>>(xln,  hxln, (long)SB_*E_);               /* 2 */
    cvt_h_k<<<2048,256>>>(Wih,  hWih, (long)G4_*E_);               /* 3 */

    gemm_h<<<dim3(32,128,1),256>>>(hxln,hWih,bih,bhh,0, gx,        /* 4 */
        E_, E_,E_,G4_,0, 0,0,0,0, 0, 1.0f, 0);

    vs_proj_k<<<256,256>>>(vs_p,op_W,op_b);
    vs_gate_k<<<4,256>>>();
    zero_state_k<<<32,256>>>();

    lstm_persist_k<<<LSTM_BLOCKS,256,LSTM_SMEM_BYTES>>>(gx, Whh, rnn);

    ln_kernel<<<SB_,256>>>(rnn, mh,   lnmem_g, lnmem_b);
    ln_kernel<<<SB_,256>>>(rnn, hmid, lnmid_g, lnmid_b);
    cvt_h_k<<<2048,256>>>(hmid, hhmid, (long)SB_*E_);
    cvt_h_k<<<512,256>>>(ql_W,  hqlW, (long)E_*E_);
    cvt_h_k<<<512,256>>>(boom_W, hbmW, (long)E_*E_);

    gemm_h<<<dim3(8,128,1),256>>>(hhmid,hqlW,ql_b,0,0, qpre,
        E_, E_,E_,E_,0, 0,0,0,0, 0, 1.0f, 0);
    ln_kernel<<<SB_,256>>>(qpre, query, qln_g, qln_b);
    scale_qkv_k<<<1024,256>>>(qs, ks_p);
    vT_k<<<dim3(S_/32,E_/32,B_),256>>>();

    gemm_h<<<dim3(16,16,8),256>>>(hqsc,hksc,0,0,mask, scores,
        E_, B_*E_, B_*E_, S_, S_, E_, E_, (long)S_*S_, 0, 1, 0.03125f, 1);

    softmax_k<<<B_*S_,256>>>(scores, hsc);

    gemm_h<<<dim3(8,16,8),256>>>(hsc,hvT,0,0,hmid, h2,
        S_, S_, S_, B_*E_, B_*E_, (long)S_*S_, (long)E_*S_, E_, E_, 2, 1.0f, 1);

    ln_kernel<<<SB_,256>>>(h2, xff,   lnxff_g, lnxff_b);
    ln_kernel<<<SB_,256>>>(h2, lnffo, lnff_g,  lnff_b);
    cvt_h_k<<<2048,256>>>(xff, hxff, (long)SB_*E_);
    gemm_h<<<dim3(8,128,1),256>>>(hxff,hbmW,boom_b,0,lnffo, out,
        E_, E_,E_,E_,E_, 0,0,0,0, 3, 1.0f, 0);
}